// round 16
// baseline (speedup 1.0000x reference)
#include <cuda_runtime.h>
#include <cuda_fp16.h>
#include <cstdint>

#define N_EMBD 2048
#define NHEAD  16
#define HD     128
#define BATCH  2
#define TSEQ   2048
#define MTOT   (BATCH * TSEQ)
#define KDIM   N_EMBD
#define NTOT   2304
#define QSCALE 0.08838834764831845f

__device__ __half g_xh[MTOT * KDIM];
__device__ __half g_wh[NTOT * KDIM];
__device__ __half g_qh[MTOT * N_EMBD];
__device__ __half g_kh[MTOT * HD];
__device__ __half g_vt[BATCH * HD * TSEQ];

// ---------------- helpers ----------------
__device__ __forceinline__ uint32_t smem_u32(const void* p) {
    uint32_t a;
    asm("{ .reg .u64 t; cvta.to.shared.u64 t, %1; cvt.u32.u64 %0, t; }" : "=r"(a) : "l"(p));
    return a;
}
#define CP16(sm, gm)  asm volatile("cp.async.cg.shared.global [%0], [%1], 16;" :: "r"(sm), "l"(gm))
#define CP_COMMIT()   asm volatile("cp.async.commit_group;" ::: "memory")
#define CP_WAIT0()    asm volatile("cp.async.wait_group 0;" ::: "memory")

#define LDSM4(r0, r1, r2, r3, a) \
    asm volatile("ldmatrix.sync.aligned.m8n8.x4.shared.b16 {%0,%1,%2,%3}, [%4];" \
                 : "=r"(r0), "=r"(r1), "=r"(r2), "=r"(r3) : "r"(a))
#define MMA16816(c, a, b0, b1) \
    asm volatile("mma.sync.aligned.m16n8k16.row.col.f32.f16.f16.f32 " \
                 "{%0,%1,%2,%3}, {%4,%5,%6,%7}, {%8,%9}, {%0,%1,%2,%3};" \
                 : "+f"((c)[0]), "+f"((c)[1]), "+f"((c)[2]), "+f"((c)[3]) \
                 : "r"((a)[0]), "r"((a)[1]), "r"((a)[2]), "r"((a)[3]), "r"(b0), "r"(b1))

__device__ __forceinline__ uint32_t h2pack(float a, float b) {
    __half2 h = __floats2half2_rn(a, b);
    return *(uint32_t*)&h;
}
// B-operand ldmatrix x4: covers n16 x k16 (two n8k16 fragments).
__device__ __forceinline__ uint32_t bfrag_addr(uint32_t base, int lane, int nbase,
                                               int kcol, int STR) {
    int row = nbase + ((lane >> 4) << 3) + (lane & 7);
    int col = kcol + ((lane >> 3) & 1) * 8;
    return base + (uint32_t)(row * STR + col) * 2u;
}

// ---------------- kernel 0: fp32 -> fp16 (2x unrolled for MLP) ----------------
__global__ void convert_inputs(const float* __restrict__ x,
                               const float* __restrict__ wkv,
                               const float* __restrict__ wq) {
    const int stride = gridDim.x * blockDim.x;           // 262,144
    const int t0 = blockIdx.x * blockDim.x + threadIdx.x;

    auto cv8 = [](const float* src, __half* dst, int i) {
        float4 a = ((const float4*)src)[2 * i], b = ((const float4*)src)[2 * i + 1];
        *(uint4*)&dst[8 * i] = make_uint4(h2pack(a.x, a.y), h2pack(a.z, a.w),
                                          h2pack(b.x, b.y), h2pack(b.z, b.w));
    };
    // x: 1,048,576 uint4-groups = 4 strides -> 2 pair iterations
    for (int i = t0; i < MTOT * KDIM / 8; i += 2 * stride) {
        cv8(x, g_xh, i);
        cv8(x, g_xh, i + stride);
    }
    // wkv: 65,536 groups (< stride)
    for (int i = t0; i < 256 * KDIM / 8; i += stride) cv8(wkv, g_wh, i);
    // wq: 524,288 groups = 2 strides -> 1 pair iteration
    for (int i = t0; i < N_EMBD * KDIM / 8; i += 2 * stride) {
        cv8(wq, g_wh + 256 * KDIM, i);
        cv8(wq, g_wh + 256 * KDIM, i + stride);
    }
}

// ---------------- kernel 1: projection GEMM, 256x128x128, 2-stage ----------------
#define ASTR 136                         // halves per smem row (272B, conflict-free)
#define ATILE (256 * ASTR)
#define BTILE (128 * ASTR)
#define GEMM_SMEM (2 * (ATILE + BTILE) * 2)   // 208,896 B

__global__ __launch_bounds__(256, 1)
void gemm_tc() {
    extern __shared__ __half sm[];
    const uint32_t sbA = smem_u32(sm);
    const uint32_t sbB = sbA + 2 * ATILE * 2;

    const int tid = threadIdx.x, wid = tid >> 5, lane = tid & 31;
    const int n0 = blockIdx.x * 128, m0 = blockIdx.y * 256;
    const int wm = (wid & 3) * 64, wn = (wid >> 2) * 64;

    const __half* Ag = g_xh + (size_t)m0 * KDIM;
    const __half* Bg = g_wh + (size_t)n0 * KDIM;

    auto issue_full = [&](int g) {
        const uint32_t boA = (uint32_t)(g & 1) * ATILE * 2;
        const uint32_t boB = (uint32_t)(g & 1) * BTILE * 2;
#pragma unroll
        for (int i = 0; i < 16; i++) {
            int idx = tid + 256 * i, r = idx >> 4, c = idx & 15;
            CP16(sbA + boA + (uint32_t)(r * ASTR + c * 8) * 2,
                 Ag + (size_t)r * KDIM + g * 128 + c * 8);
        }
#pragma unroll
        for (int i = 0; i < 8; i++) {
            int idx = tid + 256 * i, r = idx >> 4, c = idx & 15;
            CP16(sbB + boB + (uint32_t)(r * ASTR + c * 8) * 2,
                 Bg + (size_t)r * KDIM + g * 128 + c * 8);
        }
        CP_COMMIT();
    };
    // part 0..7: issues A chunk-iters 2p,2p+1 and B chunk-iter p; commit at p==7
    auto issue_part = [&](int g, int part) {
        const uint32_t boA = (uint32_t)(g & 1) * ATILE * 2;
        const uint32_t boB = (uint32_t)(g & 1) * BTILE * 2;
#pragma unroll
        for (int i = 2 * part; i < 2 * part + 2; i++) {
            int idx = tid + 256 * i, r = idx >> 4, c = idx & 15;
            CP16(sbA + boA + (uint32_t)(r * ASTR + c * 8) * 2,
                 Ag + (size_t)r * KDIM + g * 128 + c * 8);
        }
        {
            int idx = tid + 256 * part, r = idx >> 4, c = idx & 15;
            CP16(sbB + boB + (uint32_t)(r * ASTR + c * 8) * 2,
                 Bg + (size_t)r * KDIM + g * 128 + c * 8);
        }
        if (part == 7) CP_COMMIT();
    };

    float acc[4][8][4];
#pragma unroll
    for (int mt = 0; mt < 4; mt++)
#pragma unroll
        for (int nt = 0; nt < 8; nt++)
#pragma unroll
            for (int e = 0; e < 4; e++) acc[mt][nt][e] = 0.f;

    issue_full(0);

    const int NIT = KDIM / 128;                           // 16
    for (int j = 0; j < NIT; j++) {
        CP_WAIT0();
        __syncthreads();
        const uint32_t boA = (uint32_t)(j & 1) * ATILE * 2;
        const uint32_t boB = (uint32_t)(j & 1) * BTILE * 2;
        const bool pf = (j + 1 < NIT);
#pragma unroll
        for (int ks = 0; ks < 8; ks++) {                   // 8 k16 steps
            if (pf) issue_part(j + 1, ks);                 // spread prefetch issue
            uint32_t af[4][4];
#pragma unroll
            for (int mt = 0; mt < 4; mt++) {
                uint32_t a = sbA + boA +
                    (uint32_t)((wm + mt * 16 + (lane & 15)) * ASTR + ks * 16 + (lane >> 4) * 8) * 2;
                LDSM4(af[mt][0], af[mt][1], af[mt][2], af[mt][3], a);
            }
#pragma unroll
            for (int ntp = 0; ntp < 4; ntp++) {
                uint32_t b0, b1, b2, b3;
                LDSM4(b0, b1, b2, b3,
                      bfrag_addr(sbB + boB, lane, wn + ntp * 16, ks * 16, ASTR));
#pragma unroll
                for (int mt = 0; mt < 4; mt++) {
                    MMA16816(acc[mt][2 * ntp],     af[mt], b0, b1);
                    MMA16816(acc[mt][2 * ntp + 1], af[mt], b2, b3);
                }
            }
        }
    }

    // epilogue: bx==0 -> K, bx==1 -> V(transposed), else Q (scaled)
    const int role = (blockIdx.x == 0) ? 0 : (blockIdx.x == 1) ? 1 : 2;
    const int r0 = lane >> 2, c0 = (lane & 3) * 2;
#pragma unroll
    for (int mt = 0; mt < 4; mt++) {
#pragma unroll
        for (int nt = 0; nt < 8; nt++) {
            int tokA = m0 + wm + mt * 16 + r0;
            int col = wn + nt * 8 + c0;
            float* c = acc[mt][nt];
            if (role == 0) {
                *(uint32_t*)&g_kh[(size_t)tokA * HD + col] = h2pack(c[0], c[1]);
                *(uint32_t*)&g_kh[(size_t)(tokA + 8) * HD + col] = h2pack(c[2], c[3]);
            } else if (role == 2) {
                size_t base = (size_t)tokA * N_EMBD + (n0 - 256) + col;
                *(uint32_t*)&g_qh[base] = h2pack(c[0] * QSCALE, c[1] * QSCALE);
                *(uint32_t*)&g_qh[base + 8 * N_EMBD] = h2pack(c[2] * QSCALE, c[3] * QSCALE);
            } else {
                int bA = tokA >> 11, tl = tokA & 2047;
                int bB = (tokA + 8) >> 11, tl2 = (tokA + 8) & 2047;
                g_vt[(size_t)(bA * HD + col) * TSEQ + tl] = __float2half_rn(c[0]);
                g_vt[(size_t)(bA * HD + col + 1) * TSEQ + tl] = __float2half_rn(c[1]);
                g_vt[(size_t)(bB * HD + col) * TSEQ + tl2] = __float2half_rn(c[2]);
                g_vt[(size_t)(bB * HD + col + 1) * TSEQ + tl2] = __float2half_rn(c[3]);
            }
        }
    }
}

// ---------------- kernel 2: flash attention, deferred-PV + split spread prefetch ----------------
// Tiles: K 2-ring (slots 0,1), V 3-ring (slots 2,3,4), Q staged in slot 4.
#define QSTR 136
#define TBUF (128 * QSTR)
#define ATT_SMEM (5 * TBUF * 2)           // 174,080 B

__global__ __launch_bounds__(256, 1)
void attn_tc(float* __restrict__ out) {
    extern __shared__ __half sm[];
    const uint32_t sb = smem_u32(sm);

    const int tid = threadIdx.x, wid = tid >> 5, lane = tid & 31;
    const int qt = (int)gridDim.x - 1 - (int)blockIdx.x;   // big tiles first
    const int qm0 = qt * 128;
    const int b = blockIdx.y >> 4, h = blockIdx.y & 15;

    const __half* Qg = g_qh + (size_t)(b * TSEQ + qm0) * N_EMBD + h * HD;
    const __half* Kg = g_kh + (size_t)b * TSEQ * HD;
    const __half* Vg = g_vt + (size_t)b * HD * TSEQ;

    auto tileK = [&](int j) -> uint32_t { return sb + (uint32_t)(j & 1) * TBUF * 2u; };
    auto tileV = [&](int j) -> uint32_t { return sb + (uint32_t)(2 + j % 3) * TBUF * 2u; };

    auto issueK_part = [&](int j, int part) {
        const uint32_t kb = tileK(j);
        int id = tid + 256 * part, r = id >> 4, c = id & 15;
        CP16(kb + (uint32_t)(r * QSTR + c * 8) * 2,
             Kg + (size_t)(j * 128 + r) * HD + c * 8);
    };
    auto issueV_part = [&](int j, int part) {
        const uint32_t vb = tileV(j);
        int id = tid + 256 * part, r = id >> 4, c = id & 15;
        CP16(vb + (uint32_t)(r * QSTR + c * 8) * 2,
             Vg + (size_t)r * TSEQ + j * 128 + c * 8);
    };
    auto issue_full = [&](int j) {
#pragma unroll
        for (int i = 0; i < 8; i++) issueK_part(j, i);
#pragma unroll
        for (int i = 0; i < 8; i++) issueV_part(j, i);
        CP_COMMIT();
    };

    // stage Q into slot 4 (V(2)'s slot; overwritten first at iter 1, after extraction)
#pragma unroll
    for (int i = 0; i < 8; i++) {
        int id = tid + 256 * i, r = id >> 4, c = id & 15;
        *(uint4*)&sm[4 * TBUF + r * QSTR + c * 8] =
            *(const uint4*)(Qg + (size_t)r * N_EMBD + c * 8);
    }
    const int nch = qt + 1;
    issue_full(0);
    __syncthreads();                                       // Q visible

    uint32_t qa[8][4];
#pragma unroll
    for (int kt = 0; kt < 8; kt++) {
        uint32_t a = sb + 4 * TBUF * 2u +
            (uint32_t)((wid * 16 + (lane & 15)) * QSTR + kt * 16 + (lane >> 4) * 8) * 2;
        LDSM4(qa[kt][0], qa[kt][1], qa[kt][2], qa[kt][3], a);
    }

    float o[16][4];
#pragma unroll
    for (int nt = 0; nt < 16; nt++)
#pragma unroll
        for (int e = 0; e < 4; e++) o[nt][e] = 0.f;
    float m_lo = -1e30f, m_hi = -1e30f, l_lo = 0.f, l_hi = 0.f;
    float al_lo = 1.f, al_hi = 1.f;
    float s[16][4];
    uint32_t pa[8][4];

    const int rowl = wid * 16 + (lane >> 2);               // local row (and +8)

    // S = Q @ K^T; interleaves K-prefetch for chunk jn (if >= 0), 1 CP16/step
    auto computeS = [&](uint32_t kb, int jn) {
#pragma unroll
        for (int nt = 0; nt < 16; nt++) { s[nt][0] = s[nt][1] = s[nt][2] = s[nt][3] = 0.f; }
#pragma unroll
        for (int ntp = 0; ntp < 8; ntp++) {
            if (jn >= 0) issueK_part(jn, ntp);
#pragma unroll
            for (int kt = 0; kt < 8; kt++) {
                uint32_t b0, b1, b2, b3;
                LDSM4(b0, b1, b2, b3, bfrag_addr(kb, lane, ntp * 16, kt * 16, QSTR));
                MMA16816(s[2 * ntp],     qa[kt], b0, b1);
                MMA16816(s[2 * ntp + 1], qa[kt], b2, b3);
            }
        }
    };
    auto maskDiag = [&]() {
#pragma unroll
        for (int nt = 0; nt < 16; nt++) {
            int cl = nt * 8 + (lane & 3) * 2;
            if (cl > rowl)         s[nt][0] = -1e30f;
            if (cl + 1 > rowl)     s[nt][1] = -1e30f;
            if (cl > rowl + 8)     s[nt][2] = -1e30f;
            if (cl + 1 > rowl + 8) s[nt][3] = -1e30f;
        }
    };
    // O += P @ V; interleaves V-prefetch for chunk jn (commit at step 7 covers K+V)
    auto addPV = [&](uint32_t vb, int jn) {
#pragma unroll
        for (int ntp = 0; ntp < 8; ntp++) {
            if (jn >= 0) {
                issueV_part(jn, ntp);
                if (ntp == 7) CP_COMMIT();
            }
#pragma unroll
            for (int kt = 0; kt < 8; kt++) {
                uint32_t b0, b1, b2, b3;
                LDSM4(b0, b1, b2, b3, bfrag_addr(vb, lane, ntp * 16, kt * 16, QSTR));
                MMA16816(o[2 * ntp],     pa[kt], b0, b1);
                MMA16816(o[2 * ntp + 1], pa[kt], b2, b3);
            }
        }
    };
    auto softmaxUpd = [&]() {
        float mx_lo = -1e30f, mx_hi = -1e30f;
#pragma unroll
        for (int nt = 0; nt < 16; nt++) {
            mx_lo = fmaxf(mx_lo, fmaxf(s[nt][0], s[nt][1]));
            mx_hi = fmaxf(mx_hi, fmaxf(s[nt][2], s[nt][3]));
        }
        mx_lo = fmaxf(mx_lo, __shfl_xor_sync(0xffffffffu, mx_lo, 1));
        mx_lo = fmaxf(mx_lo, __shfl_xor_sync(0xffffffffu, mx_lo, 2));
        mx_hi = fmaxf(mx_hi, __shfl_xor_sync(0xffffffffu, mx_hi, 1));
        mx_hi = fmaxf(mx_hi, __shfl_xor_sync(0xffffffffu, mx_hi, 2));
        float mn_lo = fmaxf(m_lo, mx_lo), mn_hi = fmaxf(m_hi, mx_hi);
        al_lo = __expf(m_lo - mn_lo); al_hi = __expf(m_hi - mn_hi);
        m_lo = mn_lo; m_hi = mn_hi;
        float sa_lo = 0.f, sa_hi = 0.f;
#pragma unroll
        for (int nt = 0; nt < 16; nt++) {
            s[nt][0] = __expf(s[nt][0] - mn_lo);
            s[nt][1] = __expf(s[nt][1] - mn_lo);
            s[nt][2] = __expf(s[nt][2] - mn_hi);
            s[nt][3] = __expf(s[nt][3] - mn_hi);
            sa_lo += s[nt][0] + s[nt][1];
            sa_hi += s[nt][2] + s[nt][3];
        }
        sa_lo += __shfl_xor_sync(0xffffffffu, sa_lo, 1);
        sa_lo += __shfl_xor_sync(0xffffffffu, sa_lo, 2);
        sa_hi += __shfl_xor_sync(0xffffffffu, sa_hi, 1);
        sa_hi += __shfl_xor_sync(0xffffffffu, sa_hi, 2);
        l_lo = l_lo * al_lo + sa_lo;
        l_hi = l_hi * al_hi + sa_hi;
    };
    auto packP = [&]() {
#pragma unroll
        for (int kt = 0; kt < 8; kt++) {
            pa[kt][0] = h2pack(s[2 * kt][0], s[2 * kt][1]);
            pa[kt][1] = h2pack(s[2 * kt][2], s[2 * kt][3]);
            pa[kt][2] = h2pack(s[2 * kt + 1][0], s[2 * kt + 1][1]);
            pa[kt][3] = h2pack(s[2 * kt + 1][2], s[2 * kt + 1][3]);
        }
    };

    // ---- peel j = 0 (no PV yet; V(1) prefetch bursts after S) ----
    CP_WAIT0();
    __syncthreads();
    computeS(tileK(0), (nch > 1) ? 1 : -1);
    if (nch > 1) {
#pragma unroll
        for (int i = 0; i < 8; i++) issueV_part(1, i);
        CP_COMMIT();
    }
    if (qt == 0) maskDiag();
    softmaxUpd();
    packP();

    // ---- main loop: S(j) ; PV(j-1) + softmax(j) ----
    for (int j = 1; j < nch; j++) {
        CP_WAIT0();
        __syncthreads();
        const int jn = (j + 1 < nch) ? j + 1 : -1;
        computeS(tileK(j), jn);
        if (j == qt) maskDiag();
        addPV(tileV(j - 1), jn);   // V-prefetch spread here; commit covers K+V
        softmaxUpd();
        packP();
        if (!__all_sync(0xffffffffu, (al_lo == 1.0f) && (al_hi == 1.0f))) {
#pragma unroll
            for (int nt = 0; nt < 16; nt++) {
                o[nt][0] *= al_lo; o[nt][1] *= al_lo;
                o[nt][2] *= al_hi; o[nt][3] *= al_hi;
            }
        }
    }
    addPV(tileV(nch - 1), -1);     // final PV

    // epilogue
    const float inv_lo = 1.0f / l_lo, inv_hi = 1.0f / l_hi;
    const size_t rA = (size_t)(b * TSEQ + qm0 + rowl) * N_EMBD + h * HD + (lane & 3) * 2;
    const size_t rB = rA + 8 * N_EMBD;
#pragma unroll
    for (int nt = 0; nt < 16; nt++) {
        *(float2*)&out[rA + nt * 8] = make_float2(o[nt][0] * inv_lo, o[nt][1] * inv_lo);
        *(float2*)&out[rB + nt * 8] = make_float2(o[nt][2] * inv_hi, o[nt][3] * inv_hi);
    }
}

// ---------------------------------------------------------------------------
extern "C" void kernel_launch(void* const* d_in, const int* in_sizes, int n_in,
                              void* d_out, int out_size) {
    const float* x    = (const float*)d_in[0];
    const float* w_kv = (const float*)d_in[1];
    const float* w_q  = (const float*)d_in[2];
    float* out = (float*)d_out;

    cudaFuncSetAttribute(gemm_tc, cudaFuncAttributeMaxDynamicSharedMemorySize, GEMM_SMEM);
    cudaFuncSetAttribute(attn_tc, cudaFuncAttributeMaxDynamicSharedMemorySize, ATT_SMEM);

    convert_inputs<<<1024, 256>>>(x, w_kv, w_q);
    dim3 g1(NTOT / 128, MTOT / 256);        // (18, 16)
    gemm_tc<<<g1, 256, GEMM_SMEM>>>();
    dim3 g2(TSEQ / 128, BATCH * NHEAD);     // (16, 32)
    attn_tc<<<g2, 256, ATT_SMEM>>>(out);
}

// round 17
// speedup vs baseline: 1.1932x; 1.1932x over previous
#include <cuda_runtime.h>
#include <cuda_fp16.h>
#include <cstdint>

#define N_EMBD 2048
#define NHEAD  16
#define HD     128
#define BATCH  2
#define TSEQ   2048
#define MTOT   (BATCH * TSEQ)
#define KDIM   N_EMBD
#define NTOT   2304
#define QSCALE 0.08838834764831845f
#define NTILES 512

__device__ __half g_xh[MTOT * KDIM];
__device__ __half g_wh[NTOT * KDIM];
__device__ __half g_qh[MTOT * N_EMBD];
__device__ __half g_kh[MTOT * HD];
__device__ __half g_vt[BATCH * HD * TSEQ];
__device__ int    g_ctr;

// ---------------- helpers ----------------
__device__ __forceinline__ uint32_t smem_u32(const void* p) {
    uint32_t a;
    asm("{ .reg .u64 t; cvta.to.shared.u64 t, %1; cvt.u32.u64 %0, t; }" : "=r"(a) : "l"(p));
    return a;
}
#define CP16(sm, gm)  asm volatile("cp.async.cg.shared.global [%0], [%1], 16;" :: "r"(sm), "l"(gm))
#define CP_COMMIT()   asm volatile("cp.async.commit_group;" ::: "memory")
#define CP_WAIT0()    asm volatile("cp.async.wait_group 0;" ::: "memory")

#define LDSM4(r0, r1, r2, r3, a) \
    asm volatile("ldmatrix.sync.aligned.m8n8.x4.shared.b16 {%0,%1,%2,%3}, [%4];" \
                 : "=r"(r0), "=r"(r1), "=r"(r2), "=r"(r3) : "r"(a))
#define MMA16816(c, a, b0, b1) \
    asm volatile("mma.sync.aligned.m16n8k16.row.col.f32.f16.f16.f32 " \
                 "{%0,%1,%2,%3}, {%4,%5,%6,%7}, {%8,%9}, {%0,%1,%2,%3};" \
                 : "+f"((c)[0]), "+f"((c)[1]), "+f"((c)[2]), "+f"((c)[3]) \
                 : "r"((a)[0]), "r"((a)[1]), "r"((a)[2]), "r"((a)[3]), "r"(b0), "r"(b1))

__device__ __forceinline__ uint32_t h2pack(float a, float b) {
    __half2 h = __floats2half2_rn(a, b);
    return *(uint32_t*)&h;
}
// B-operand ldmatrix x4: covers n16 x k16 (two n8k16 fragments).
__device__ __forceinline__ uint32_t bfrag_addr(uint32_t base, int lane, int nbase,
                                               int kcol, int STR) {
    int row = nbase + ((lane >> 4) << 3) + (lane & 7);
    int col = kcol + ((lane >> 3) & 1) * 8;
    return base + (uint32_t)(row * STR + col) * 2u;
}

// ---------------- kernel 0: fp32 -> fp16 (also resets tile counter) ----------------
__global__ void convert_inputs(const float* __restrict__ x,
                               const float* __restrict__ wkv,
                               const float* __restrict__ wq) {
    if (blockIdx.x == 0 && threadIdx.x == 0) g_ctr = 0;
    const int stride = gridDim.x * blockDim.x;
    const int t0 = blockIdx.x * blockDim.x + threadIdx.x;
    for (int i = t0; i < MTOT * KDIM / 8; i += stride) {
        float4 a = ((const float4*)x)[2 * i], b = ((const float4*)x)[2 * i + 1];
        *(uint4*)&g_xh[8 * i] = make_uint4(h2pack(a.x, a.y), h2pack(a.z, a.w),
                                           h2pack(b.x, b.y), h2pack(b.z, b.w));
    }
    for (int i = t0; i < 256 * KDIM / 8; i += stride) {
        float4 a = ((const float4*)wkv)[2 * i], b = ((const float4*)wkv)[2 * i + 1];
        *(uint4*)&g_wh[8 * i] = make_uint4(h2pack(a.x, a.y), h2pack(a.z, a.w),
                                           h2pack(b.x, b.y), h2pack(b.z, b.w));
    }
    for (int i = t0; i < N_EMBD * KDIM / 8; i += stride) {
        float4 a = ((const float4*)wq)[2 * i], b = ((const float4*)wq)[2 * i + 1];
        *(uint4*)&g_wh[256 * KDIM + 8 * i] =
            make_uint4(h2pack(a.x, a.y), h2pack(a.z, a.w),
                       h2pack(b.x, b.y), h2pack(b.z, b.w));
    }
}

// ---------------- kernel 1: projection GEMM, 256x128x128, 2-stage ----------------
#define ASTR 136                         // halves per smem row (272B, conflict-free)
#define ATILE (256 * ASTR)
#define BTILE (128 * ASTR)
#define GEMM_SMEM (2 * (ATILE + BTILE) * 2)   // 208,896 B

__global__ __launch_bounds__(256, 1)
void gemm_tc() {
    extern __shared__ __half sm[];
    const uint32_t sbA = smem_u32(sm);
    const uint32_t sbB = sbA + 2 * ATILE * 2;

    const int tid = threadIdx.x, wid = tid >> 5, lane = tid & 31;
    const int n0 = blockIdx.x * 128, m0 = blockIdx.y * 256;
    const int wm = (wid & 3) * 64, wn = (wid >> 2) * 64;

    const __half* Ag = g_xh + (size_t)m0 * KDIM;
    const __half* Bg = g_wh + (size_t)n0 * KDIM;

    auto issue_full = [&](int g) {
        const uint32_t boA = (uint32_t)(g & 1) * ATILE * 2;
        const uint32_t boB = (uint32_t)(g & 1) * BTILE * 2;
#pragma unroll
        for (int i = 0; i < 16; i++) {
            int idx = tid + 256 * i, r = idx >> 4, c = idx & 15;
            CP16(sbA + boA + (uint32_t)(r * ASTR + c * 8) * 2,
                 Ag + (size_t)r * KDIM + g * 128 + c * 8);
        }
#pragma unroll
        for (int i = 0; i < 8; i++) {
            int idx = tid + 256 * i, r = idx >> 4, c = idx & 15;
            CP16(sbB + boB + (uint32_t)(r * ASTR + c * 8) * 2,
                 Bg + (size_t)r * KDIM + g * 128 + c * 8);
        }
        CP_COMMIT();
    };
    // part 0..7: issues A chunk-iters 2p,2p+1 and B chunk-iter p; commit at p==7
    auto issue_part = [&](int g, int part) {
        const uint32_t boA = (uint32_t)(g & 1) * ATILE * 2;
        const uint32_t boB = (uint32_t)(g & 1) * BTILE * 2;
#pragma unroll
        for (int i = 2 * part; i < 2 * part + 2; i++) {
            int idx = tid + 256 * i, r = idx >> 4, c = idx & 15;
            CP16(sbA + boA + (uint32_t)(r * ASTR + c * 8) * 2,
                 Ag + (size_t)r * KDIM + g * 128 + c * 8);
        }
        {
            int idx = tid + 256 * part, r = idx >> 4, c = idx & 15;
            CP16(sbB + boB + (uint32_t)(r * ASTR + c * 8) * 2,
                 Bg + (size_t)r * KDIM + g * 128 + c * 8);
        }
        if (part == 7) CP_COMMIT();
    };

    float acc[4][8][4];
#pragma unroll
    for (int mt = 0; mt < 4; mt++)
#pragma unroll
        for (int nt = 0; nt < 8; nt++)
#pragma unroll
            for (int e = 0; e < 4; e++) acc[mt][nt][e] = 0.f;

    issue_full(0);

    const int NIT = KDIM / 128;                           // 16
    for (int j = 0; j < NIT; j++) {
        CP_WAIT0();
        __syncthreads();
        const uint32_t boA = (uint32_t)(j & 1) * ATILE * 2;
        const uint32_t boB = (uint32_t)(j & 1) * BTILE * 2;
        const bool pf = (j + 1 < NIT);
#pragma unroll
        for (int ks = 0; ks < 8; ks++) {                   // 8 k16 steps
            if (pf) issue_part(j + 1, ks);                 // spread prefetch issue
            uint32_t af[4][4];
#pragma unroll
            for (int mt = 0; mt < 4; mt++) {
                uint32_t a = sbA + boA +
                    (uint32_t)((wm + mt * 16 + (lane & 15)) * ASTR + ks * 16 + (lane >> 4) * 8) * 2;
                LDSM4(af[mt][0], af[mt][1], af[mt][2], af[mt][3], a);
            }
#pragma unroll
            for (int ntp = 0; ntp < 4; ntp++) {
                uint32_t b0, b1, b2, b3;
                LDSM4(b0, b1, b2, b3,
                      bfrag_addr(sbB + boB, lane, wn + ntp * 16, ks * 16, ASTR));
#pragma unroll
                for (int mt = 0; mt < 4; mt++) {
                    MMA16816(acc[mt][2 * ntp],     af[mt], b0, b1);
                    MMA16816(acc[mt][2 * ntp + 1], af[mt], b2, b3);
                }
            }
        }
    }

    // epilogue: bx==0 -> K, bx==1 -> V(transposed), else Q (scaled)
    const int role = (blockIdx.x == 0) ? 0 : (blockIdx.x == 1) ? 1 : 2;
    const int r0 = lane >> 2, c0 = (lane & 3) * 2;
#pragma unroll
    for (int mt = 0; mt < 4; mt++) {
#pragma unroll
        for (int nt = 0; nt < 8; nt++) {
            int tokA = m0 + wm + mt * 16 + r0;
            int col = wn + nt * 8 + c0;
            float* c = acc[mt][nt];
            if (role == 0) {
                *(uint32_t*)&g_kh[(size_t)tokA * HD + col] = h2pack(c[0], c[1]);
                *(uint32_t*)&g_kh[(size_t)(tokA + 8) * HD + col] = h2pack(c[2], c[3]);
            } else if (role == 2) {
                size_t base = (size_t)tokA * N_EMBD + (n0 - 256) + col;
                *(uint32_t*)&g_qh[base] = h2pack(c[0] * QSCALE, c[1] * QSCALE);
                *(uint32_t*)&g_qh[base + 8 * N_EMBD] = h2pack(c[2] * QSCALE, c[3] * QSCALE);
            } else {
                int bA = tokA >> 11, tl = tokA & 2047;
                int bB = (tokA + 8) >> 11, tl2 = (tokA + 8) & 2047;
                g_vt[(size_t)(bA * HD + col) * TSEQ + tl] = __float2half_rn(c[0]);
                g_vt[(size_t)(bA * HD + col + 1) * TSEQ + tl] = __float2half_rn(c[1]);
                g_vt[(size_t)(bB * HD + col) * TSEQ + tl2] = __float2half_rn(c[2]);
                g_vt[(size_t)(bB * HD + col + 1) * TSEQ + tl2] = __float2half_rn(c[3]);
            }
        }
    }
}

// ---------------- kernel 2: persistent flash attention (dynamic LPT scheduler) ----------------
// Tiles: K 2-ring (slots 0,1), V 3-ring (slots 2,3,4), Q staged in slot 4.
#define QSTR 136
#define TBUF (128 * QSTR)
#define ATT_SMEM (5 * TBUF * 2)           // 174,080 B dynamic

__global__ __launch_bounds__(256, 1)
void attn_tc(float* __restrict__ out) {
    extern __shared__ __half sm[];
    __shared__ int s_w;
    const uint32_t sb = smem_u32(sm);
    const int tid = threadIdx.x, wid = tid >> 5, lane = tid & 31;
    const int rowl = wid * 16 + (lane >> 2);               // local row (and +8)

    while (true) {
        if (tid == 0) s_w = atomicAdd(&g_ctr, 1);
        __syncthreads();                                   // broadcast + end-of-prev-tile barrier
        const int w = s_w;
        if (w >= NTILES) return;

        const int qt = 15 - (w >> 5);                      // heavy tiles handed out first
        const int byh = w & 31;
        const int qm0 = qt * 128;
        const int b = byh >> 4, h = byh & 15;

        const __half* Qg = g_qh + (size_t)(b * TSEQ + qm0) * N_EMBD + h * HD;
        const __half* Kg = g_kh + (size_t)b * TSEQ * HD;
        const __half* Vg = g_vt + (size_t)b * HD * TSEQ;

        auto tileK = [&](int j) -> uint32_t { return sb + (uint32_t)(j & 1) * TBUF * 2u; };
        auto tileV = [&](int j) -> uint32_t { return sb + (uint32_t)(2 + j % 3) * TBUF * 2u; };

        auto issue_full = [&](int j) {
            const uint32_t kb = tileK(j), vb = tileV(j);
#pragma unroll
            for (int i = 0; i < 8; i++) {
                int id = tid + 256 * i, r = id >> 4, c = id & 15;
                CP16(kb + (uint32_t)(r * QSTR + c * 8) * 2,
                     Kg + (size_t)(j * 128 + r) * HD + c * 8);
            }
#pragma unroll
            for (int i = 0; i < 8; i++) {
                int id = tid + 256 * i, r = id >> 4, c = id & 15;
                CP16(vb + (uint32_t)(r * QSTR + c * 8) * 2,
                     Vg + (size_t)r * TSEQ + j * 128 + c * 8);
            }
            CP_COMMIT();
        };
        // part 0..7: issues K chunk-iter p and V chunk-iter p; commit at p==7
        auto issue_part = [&](int j, int part) {
            const uint32_t kb = tileK(j), vb = tileV(j);
            int id = tid + 256 * part, r = id >> 4, c = id & 15;
            CP16(kb + (uint32_t)(r * QSTR + c * 8) * 2,
                 Kg + (size_t)(j * 128 + r) * HD + c * 8);
            CP16(vb + (uint32_t)(r * QSTR + c * 8) * 2,
                 Vg + (size_t)r * TSEQ + j * 128 + c * 8);
            if (part == 7) CP_COMMIT();
        };

        // stage Q into slot 4 (V(2)'s slot; overwritten first at iter 1, after extraction)
#pragma unroll
        for (int i = 0; i < 8; i++) {
            int id = tid + 256 * i, r = id >> 4, c = id & 15;
            *(uint4*)&sm[4 * TBUF + r * QSTR + c * 8] =
                *(const uint4*)(Qg + (size_t)r * N_EMBD + c * 8);
        }
        const int nch = qt + 1;
        issue_full(0);
        __syncthreads();                                   // Q visible

        uint32_t qa[8][4];
#pragma unroll
        for (int kt = 0; kt < 8; kt++) {
            uint32_t a = sb + 4 * TBUF * 2u +
                (uint32_t)((wid * 16 + (lane & 15)) * QSTR + kt * 16 + (lane >> 4) * 8) * 2;
            LDSM4(qa[kt][0], qa[kt][1], qa[kt][2], qa[kt][3], a);
        }

        float o[16][4];
#pragma unroll
        for (int nt = 0; nt < 16; nt++)
#pragma unroll
            for (int e = 0; e < 4; e++) o[nt][e] = 0.f;
        float m_lo = -1e30f, m_hi = -1e30f, l_lo = 0.f, l_hi = 0.f;
        float al_lo = 1.f, al_hi = 1.f;
        float s[16][4];
        uint32_t pa[8][4];

        auto computeS = [&](uint32_t kb, int jn) {
#pragma unroll
            for (int nt = 0; nt < 16; nt++) { s[nt][0] = s[nt][1] = s[nt][2] = s[nt][3] = 0.f; }
#pragma unroll
            for (int ntp = 0; ntp < 8; ntp++) {
                if (jn >= 0) issue_part(jn, ntp);
#pragma unroll
                for (int kt = 0; kt < 8; kt++) {
                    uint32_t b0, b1, b2, b3;
                    LDSM4(b0, b1, b2, b3, bfrag_addr(kb, lane, ntp * 16, kt * 16, QSTR));
                    MMA16816(s[2 * ntp],     qa[kt], b0, b1);
                    MMA16816(s[2 * ntp + 1], qa[kt], b2, b3);
                }
            }
        };
        auto maskDiag = [&]() {
#pragma unroll
            for (int nt = 0; nt < 16; nt++) {
                int cl = nt * 8 + (lane & 3) * 2;
                if (cl > rowl)         s[nt][0] = -1e30f;
                if (cl + 1 > rowl)     s[nt][1] = -1e30f;
                if (cl > rowl + 8)     s[nt][2] = -1e30f;
                if (cl + 1 > rowl + 8) s[nt][3] = -1e30f;
            }
        };
        auto addPV = [&](uint32_t vb) {
#pragma unroll
            for (int ntp = 0; ntp < 8; ntp++) {
#pragma unroll
                for (int kt = 0; kt < 8; kt++) {
                    uint32_t b0, b1, b2, b3;
                    LDSM4(b0, b1, b2, b3, bfrag_addr(vb, lane, ntp * 16, kt * 16, QSTR));
                    MMA16816(o[2 * ntp],     pa[kt], b0, b1);
                    MMA16816(o[2 * ntp + 1], pa[kt], b2, b3);
                }
            }
        };
        auto softmaxUpd = [&]() {
            float mx_lo = -1e30f, mx_hi = -1e30f;
#pragma unroll
            for (int nt = 0; nt < 16; nt++) {
                mx_lo = fmaxf(mx_lo, fmaxf(s[nt][0], s[nt][1]));
                mx_hi = fmaxf(mx_hi, fmaxf(s[nt][2], s[nt][3]));
            }
            mx_lo = fmaxf(mx_lo, __shfl_xor_sync(0xffffffffu, mx_lo, 1));
            mx_lo = fmaxf(mx_lo, __shfl_xor_sync(0xffffffffu, mx_lo, 2));
            mx_hi = fmaxf(mx_hi, __shfl_xor_sync(0xffffffffu, mx_hi, 1));
            mx_hi = fmaxf(mx_hi, __shfl_xor_sync(0xffffffffu, mx_hi, 2));
            float mn_lo = fmaxf(m_lo, mx_lo), mn_hi = fmaxf(m_hi, mx_hi);
            al_lo = __expf(m_lo - mn_lo); al_hi = __expf(m_hi - mn_hi);
            m_lo = mn_lo; m_hi = mn_hi;
            float sa_lo = 0.f, sa_hi = 0.f;
#pragma unroll
            for (int nt = 0; nt < 16; nt++) {
                s[nt][0] = __expf(s[nt][0] - mn_lo);
                s[nt][1] = __expf(s[nt][1] - mn_lo);
                s[nt][2] = __expf(s[nt][2] - mn_hi);
                s[nt][3] = __expf(s[nt][3] - mn_hi);
                sa_lo += s[nt][0] + s[nt][1];
                sa_hi += s[nt][2] + s[nt][3];
            }
            sa_lo += __shfl_xor_sync(0xffffffffu, sa_lo, 1);
            sa_lo += __shfl_xor_sync(0xffffffffu, sa_lo, 2);
            sa_hi += __shfl_xor_sync(0xffffffffu, sa_hi, 1);
            sa_hi += __shfl_xor_sync(0xffffffffu, sa_hi, 2);
            l_lo = l_lo * al_lo + sa_lo;
            l_hi = l_hi * al_hi + sa_hi;
        };
        auto packP = [&]() {
#pragma unroll
            for (int kt = 0; kt < 8; kt++) {
                pa[kt][0] = h2pack(s[2 * kt][0], s[2 * kt][1]);
                pa[kt][1] = h2pack(s[2 * kt][2], s[2 * kt][3]);
                pa[kt][2] = h2pack(s[2 * kt + 1][0], s[2 * kt + 1][1]);
                pa[kt][3] = h2pack(s[2 * kt + 1][2], s[2 * kt + 1][3]);
            }
        };

        // ---- peel j = 0 ----
        CP_WAIT0();
        __syncthreads();
        computeS(tileK(0), (nch > 1) ? 1 : -1);
        if (qt == 0) maskDiag();
        softmaxUpd();
        packP();

        // ---- main loop: S(j) ; PV(j-1) + softmax(j) ----
        for (int j = 1; j < nch; j++) {
            CP_WAIT0();
            __syncthreads();
            computeS(tileK(j), (j + 1 < nch) ? j + 1 : -1);
            if (j == qt) maskDiag();
            addPV(tileV(j - 1));
            softmaxUpd();
            packP();
            if (!__all_sync(0xffffffffu, (al_lo == 1.0f) && (al_hi == 1.0f))) {
#pragma unroll
                for (int nt = 0; nt < 16; nt++) {
                    o[nt][0] *= al_lo; o[nt][1] *= al_lo;
                    o[nt][2] *= al_hi; o[nt][3] *= al_hi;
                }
            }
        }
        addPV(tileV(nch - 1));     // final PV

        // epilogue
        const float inv_lo = 1.0f / l_lo, inv_hi = 1.0f / l_hi;
        const size_t rA = (size_t)(b * TSEQ + qm0 + rowl) * N_EMBD + h * HD + (lane & 3) * 2;
        const size_t rB = rA + 8 * N_EMBD;
#pragma unroll
        for (int nt = 0; nt < 16; nt++) {
            *(float2*)&out[rA + nt * 8] = make_float2(o[nt][0] * inv_lo, o[nt][1] * inv_lo);
            *(float2*)&out[rB + nt * 8] = make_float2(o[nt][2] * inv_hi, o[nt][3] * inv_hi);
        }
    }
}

// ---------------------------------------------------------------------------
extern "C" void kernel_launch(void* const* d_in, const int* in_sizes, int n_in,
                              void* d_out, int out_size) {
    const float* x    = (const float*)d_in[0];
    const float* w_kv = (const float*)d_in[1];
    const float* w_q  = (const float*)d_in[2];
    float* out = (float*)d_out;

    cudaFuncSetAttribute(gemm_tc, cudaFuncAttributeMaxDynamicSharedMemorySize, GEMM_SMEM);
    cudaFuncSetAttribute(attn_tc, cudaFuncAttributeMaxDynamicSharedMemorySize, ATT_SMEM);

    convert_inputs<<<1024, 256>>>(x, w_kv, w_q);
    dim3 g1(NTOT / 128, MTOT / 256);        // (18, 16)
    gemm_tc<<<g1, 256, GEMM_SMEM>>>();
    attn_tc<<<148, 256, ATT_SMEM>>>(out);   // persistent, dynamic LPT
}